// round 16
// baseline (speedup 1.0000x reference)
#include <cuda_runtime.h>
#include <cuda_bf16.h>
#include <cstdint>

// SpatialCNN: 4 directional scans; step: out[p] += relu(conv1d_C2C(out[p_prev]))
// bf16 hi/lo split (3-MMA) mma.sync.m16n8k16, fp32 accumulate, in-place.
// R15: FAT WARP TILES (MF=2 H / MF=3 W) to double/triple MMAs per operand load,
// + K-split teams to keep 4 warps/SMSP. Attacks the operand-delivery duty cap.

#define B_ 64
#define C_ 128
#define H_ 36
#define W_ 100
#define KS_ 9
#define CH_STRIDE (H_ * W_)
#define B_STRIDE  (C_ * H_ * W_)

#define ROWB 272
#define ROWE 136

// Prepacked weights: [((dir*9+s)*8 + cif)*16 + co8][lane] = uint4
__device__ uint4 g_wPack[4 * 72 * 16 * 32];

__device__ __forceinline__ uint32_t pk_hi(float a, float b) {
    __nv_bfloat16 ha = __float2bfloat16(a), hb = __float2bfloat16(b);
    return (uint32_t)__bfloat16_as_ushort(ha) |
           ((uint32_t)__bfloat16_as_ushort(hb) << 16);
}
__device__ __forceinline__ float bf_res(float v) {
    return v - __bfloat162float(__float2bfloat16(v));
}

__global__ void prepack_kernel(const float* __restrict__ wd,
                               const float* __restrict__ wu,
                               const float* __restrict__ wr,
                               const float* __restrict__ wl) {
    int idx = blockIdx.x * 256 + threadIdx.x;
    const int total = 4 * 72 * 16 * 32;
    if (idx >= total) return;
    int lane = idx & 31;
    int fr   = idx >> 5;
    int co8  = fr & 15;
    int cif  = (fr >> 4) & 7;
    int rem  = fr >> 7;
    int s    = rem % 9;
    int dir  = rem / 9;
    const float* w = (dir == 0) ? wd : (dir == 1) ? wu : (dir == 2) ? wr : wl;

    int co = co8 * 8 + (lane >> 2);
    int ci = cif * 16 + (lane & 3) * 2;
    float v00 = w[(co * C_ + ci    ) * KS_ + s];
    float v01 = w[(co * C_ + ci + 1) * KS_ + s];
    float v10 = w[(co * C_ + ci + 8) * KS_ + s];
    float v11 = w[(co * C_ + ci + 9) * KS_ + s];

    uint4 r;
    r.x = pk_hi(v00, v01);
    r.y = pk_hi(v10, v11);
    r.z = pk_hi(bf_res(v00), bf_res(v01));
    r.w = pk_hi(bf_res(v10), bf_res(v11));
    g_wPack[idx] = r;
}

__device__ __forceinline__ void ldsm4(uint32_t a[4], uint32_t addr) {
    asm volatile("ldmatrix.sync.aligned.m8n8.x4.shared.b16 {%0,%1,%2,%3}, [%4];"
                 : "=r"(a[0]), "=r"(a[1]), "=r"(a[2]), "=r"(a[3]) : "r"(addr));
}
__device__ __forceinline__ void mma16816(float c[4], const uint32_t a[4],
                                         uint32_t b0, uint32_t b1) {
    asm volatile(
        "mma.sync.aligned.m16n8k16.row.col.f32.bf16.bf16.f32 "
        "{%0,%1,%2,%3},{%4,%5,%6,%7},{%8,%9},{%0,%1,%2,%3};"
        : "+f"(c[0]), "+f"(c[1]), "+f"(c[2]), "+f"(c[3])
        : "r"(a[0]), "r"(a[1]), "r"(a[2]), "r"(a[3]), "r"(b0), "r"(b1));
}

// Partial GEMM over idx in [idx0, idx1): MF m16 line-frags x COF co8-frags,
// B 1-ahead register prefetch. acc laid out [MF*COF][4].
template <int MF, int COF>
__device__ __forceinline__ void compute_range(
    uint32_t shBase, uint32_t slBase,
    const uint4* __restrict__ wpB, int co8base,
    int idx0, int idx1, float (*acc)[4])
{
    uint4 Bc[COF], Bn[COF];
#pragma unroll
    for (int f = 0; f < COF; f++)
        Bc[f] = wpB[((size_t)idx0 * 16 + co8base + f) * 32];

#pragma unroll 1
    for (int idx = idx0; idx < idx1; idx++) {
        const int nidx = (idx + 1 < idx1) ? idx + 1 : idx;
#pragma unroll
        for (int f = 0; f < COF; f++)
            Bn[f] = wpB[((size_t)nidx * 16 + co8base + f) * 32];

        const uint32_t off = (uint32_t)(idx >> 3) * ROWB + (uint32_t)(idx & 7) * 32;
        uint32_t ah[MF][4], al[MF][4];
#pragma unroll
        for (int mf = 0; mf < MF; mf++) {
            ldsm4(ah[mf], shBase + off + mf * (16 * ROWB));
            ldsm4(al[mf], slBase + off + mf * (16 * ROWB));
        }
#pragma unroll
        for (int mf = 0; mf < MF; mf++)
#pragma unroll
            for (int f = 0; f < COF; f++) {
                mma16816(acc[mf * COF + f], ah[mf], Bc[f].x, Bc[f].y);
                mma16816(acc[mf * COF + f], ah[mf], Bc[f].z, Bc[f].w);
                mma16816(acc[mf * COF + f], al[mf], Bc[f].x, Bc[f].y);
            }
#pragma unroll
        for (int f = 0; f < COF; f++) Bc[f] = Bn[f];
    }
}

template <int WINR, int L, int ES, int THREADS>
__device__ __forceinline__ void stage_window(
    unsigned short* sHi, unsigned short* sLo,
    const float* __restrict__ prevBase, int n0, int tid)
{
    for (int i = tid; i < C_ * WINR; i += THREADS) {
        int ci = i / WINR, j = i - ci * WINR;
        int line = n0 - 4 + j;
        float v = 0.0f;
        if (line >= 0 && line < L)
            v = prevBase[ci * CH_STRIDE + line * ES];
        __nv_bfloat16 h = __float2bfloat16(v);
        float r = v - __bfloat162float(h);
        sHi[j * ROWE + ci] = __bfloat16_as_ushort(h);
        sLo[j * ROWE + ci] = __bfloat16_as_ushort(__float2bfloat16(r));
    }
}

// ---------- H-step: 512 thr = 2 teams x (2 lg x 4 cg). MF=2, COF=4. ----------
// Tile 64 lines x 128 co; grid (2 tiles, 64 b). Team t: idx [36t, 36t+36).
#define WINR_H 72
#define SMEM_H (2 * WINR_H * ROWB + 8 * 32 * 32 * 4)   // 39168 + 32768 = 71936
__global__ void __launch_bounds__(512, 1)
mma_step_h(float* __restrict__ out, int dir, int prevOff, int curOff) {
    extern __shared__ unsigned short smem_u16[];
    unsigned short* sHi = smem_u16;
    unsigned short* sLo = smem_u16 + WINR_H * ROWE;
    float* red = (float*)(smem_u16 + 2 * WINR_H * ROWE);

    const int tid  = threadIdx.x;
    const int lane = tid & 31;
    const int warp = tid >> 5;
    const int b    = blockIdx.y;
    const int n0   = blockIdx.x * 64;

    stage_window<WINR_H, W_, 1, 512>(sHi, sLo,
        out + (size_t)b * B_STRIDE + prevOff, n0, tid);
    __syncthreads();

    const int team = warp >> 3;            // 0,1
    const int r    = warp & 7;
    const int lg   = r >> 2;               // 0,1 : 32-line group
    const int cg   = r & 3;                // 0..3 : 4 co8 frags
    const int line0 = n0 + lg * 32;
    const bool alive = (line0 < W_);

    float acc[8][4];
#pragma unroll
    for (int f = 0; f < 8; f++)
#pragma unroll
        for (int q = 0; q < 4; q++) acc[f][q] = 0.0f;

    if (alive) {
        const uint32_t aBase = (uint32_t)(lane & 15) * ROWB
                             + ((lane >> 4) & 1) * 16
                             + (uint32_t)(lg * 32) * ROWB;
        const uint32_t shBase = (uint32_t)__cvta_generic_to_shared(sHi) + aBase;
        const uint32_t slBase = (uint32_t)__cvta_generic_to_shared(sLo) + aBase;
        const uint4* wpB = g_wPack + (size_t)(dir * 72 * 16) * 32 + lane;
        compute_range<2, 4>(shBase, slBase, wpB, cg * 4,
                            team * 36, team * 36 + 36, acc);
    }

    float* slot = red + r * (32 * 32) + lane * 32;
    if (team == 1 && alive) {
#pragma unroll
        for (int f = 0; f < 8; f++)
            *(float4*)(slot + f * 4) = make_float4(acc[f][0], acc[f][1],
                                                   acc[f][2], acc[f][3]);
    }
    __syncthreads();
    if (team == 0 && alive) {
#pragma unroll
        for (int f = 0; f < 8; f++) {
            float4 p = *(const float4*)(slot + f * 4);
            acc[f][0] += p.x; acc[f][1] += p.y;
            acc[f][2] += p.z; acc[f][3] += p.w;
        }
        float* __restrict__ curBase = out + (size_t)b * B_STRIDE + curOff;
        const int r0 = lane >> 2;
        const int c0 = (lane & 3) * 2;
#pragma unroll
        for (int mf = 0; mf < 2; mf++) {
            const int l0 = line0 + mf * 16 + r0;
            const int l1 = l0 + 8;
#pragma unroll
            for (int f = 0; f < 4; f++) {
                const int co = (cg * 4 + f) * 8 + c0;
                float* pc = curBase + (size_t)co * CH_STRIDE;
                if (l0 < W_) {
                    pc[l0]              += fmaxf(acc[mf * 4 + f][0], 0.0f);
                    pc[l0 + CH_STRIDE] += fmaxf(acc[mf * 4 + f][1], 0.0f);
                }
                if (l1 < W_) {
                    pc[l1]              += fmaxf(acc[mf * 4 + f][2], 0.0f);
                    pc[l1 + CH_STRIDE] += fmaxf(acc[mf * 4 + f][3], 0.0f);
                }
            }
        }
    }
}

// ---------- W-step: 512 thr = 4 teams x 4 cg. MF=3, COF=2. ----------
// Rows 0-47 (36 valid), co-half per blockIdx.x. Team t: idx [18t, 18t+18).
#define WINR_W 56
#define SMEM_W (2 * WINR_W * ROWB + 12 * 32 * 24 * 4)  // 30464 + 36864 = 67328
__global__ void __launch_bounds__(512, 1)
mma_step_w(float* __restrict__ out, int dir, int prevOff, int curOff) {
    extern __shared__ unsigned short smem_u16[];
    unsigned short* sHi = smem_u16;
    unsigned short* sLo = smem_u16 + WINR_W * ROWE;
    float* red = (float*)(smem_u16 + 2 * WINR_W * ROWE);

    const int tid  = threadIdx.x;
    const int lane = tid & 31;
    const int warp = tid >> 5;
    const int b    = blockIdx.y;

    stage_window<WINR_W, H_, W_, 512>(sHi, sLo,
        out + (size_t)b * B_STRIDE + prevOff, 0, tid);
    __syncthreads();

    const int team = warp >> 2;            // 0..3
    const int cg   = warp & 3;
    const int co8base = blockIdx.x * 8 + cg * 2;

    float acc[6][4];
#pragma unroll
    for (int f = 0; f < 6; f++)
#pragma unroll
        for (int q = 0; q < 4; q++) acc[f][q] = 0.0f;

    {
        const uint32_t aBase = (uint32_t)(lane & 15) * ROWB
                             + ((lane >> 4) & 1) * 16;
        const uint32_t shBase = (uint32_t)__cvta_generic_to_shared(sHi) + aBase;
        const uint32_t slBase = (uint32_t)__cvta_generic_to_shared(sLo) + aBase;
        const uint4* wpB = g_wPack + (size_t)(dir * 72 * 16) * 32 + lane;
        compute_range<3, 2>(shBase, slBase, wpB, co8base,
                            team * 18, team * 18 + 18, acc);
    }

    float* slot = red + ((team - 1) * 4 + cg) * (32 * 24) + lane * 24;
    if (team > 0) {
#pragma unroll
        for (int f = 0; f < 6; f++)
            *(float4*)(slot + f * 4) = make_float4(acc[f][0], acc[f][1],
                                                   acc[f][2], acc[f][3]);
    }
    __syncthreads();
    if (team == 0) {
#pragma unroll
        for (int t = 0; t < 3; t++) {
            const float* s2 = red + (t * 4 + cg) * (32 * 24) + lane * 24;
#pragma unroll
            for (int f = 0; f < 6; f++) {
                float4 p = *(const float4*)(s2 + f * 4);
                acc[f][0] += p.x; acc[f][1] += p.y;
                acc[f][2] += p.z; acc[f][3] += p.w;
            }
        }
        float* __restrict__ curBase = out + (size_t)b * B_STRIDE + curOff;
        const int r0 = lane >> 2;
        const int c0 = (lane & 3) * 2;
#pragma unroll
        for (int mf = 0; mf < 3; mf++) {
            const int l0 = mf * 16 + r0;
            const int l1 = l0 + 8;
#pragma unroll
            for (int f = 0; f < 2; f++) {
                const int co = (co8base + f) * 8 + c0;
                float* pc = curBase + (size_t)co * CH_STRIDE;
                if (l0 < H_) {
                    float* p = pc + l0 * W_;
                    p[0]         += fmaxf(acc[mf * 2 + f][0], 0.0f);
                    p[CH_STRIDE] += fmaxf(acc[mf * 2 + f][1], 0.0f);
                }
                if (l1 < H_) {
                    float* p = pc + l1 * W_;
                    p[0]         += fmaxf(acc[mf * 2 + f][2], 0.0f);
                    p[CH_STRIDE] += fmaxf(acc[mf * 2 + f][3], 0.0f);
                }
            }
        }
    }
}

extern "C" void kernel_launch(void* const* d_in, const int* in_sizes, int n_in,
                              void* d_out, int out_size) {
    const float* x = (const float*)d_in[0];
    float* out = (float*)d_out;
    (void)in_sizes; (void)n_in; (void)out_size;

    cudaFuncSetAttribute((const void*)mma_step_h,
                         cudaFuncAttributeMaxDynamicSharedMemorySize, SMEM_H);
    cudaFuncSetAttribute((const void*)mma_step_w,
                         cudaFuncAttributeMaxDynamicSharedMemorySize, SMEM_W);

    // out = x (all scans accumulate in place)
    cudaMemcpyAsync(out, x, (size_t)B_ * C_ * H_ * W_ * sizeof(float),
                    cudaMemcpyDeviceToDevice, 0);

    // Pre-split + fragment-pack all weights (2.36MB, L2-resident)
    prepack_kernel<<<(4 * 72 * 16 * 32 + 255) / 256, 256>>>(
        (const float*)d_in[1], (const float*)d_in[2],
        (const float*)d_in[3], (const float*)d_in[4]);

    const dim3 gridH(2, B_);   // 2 line-tiles of 64 (tile 1 partial), all 128 co
    const dim3 gridW(2, B_);   // 2 co-halves, rows 0-47 (36 valid)

    // Scan 1: down (axis H, forward), w_d (dir 0)
    for (int h = 1; h < H_; h++)
        mma_step_h<<<gridH, 512, SMEM_H>>>(out, 0, (h - 1) * W_, h * W_);

    // Scan 2: up (axis H, reverse), w_u (dir 1)
    for (int h = H_ - 2; h >= 0; h--)
        mma_step_h<<<gridH, 512, SMEM_H>>>(out, 1, (h + 1) * W_, h * W_);

    // Scan 3: right (axis W, forward), w_r (dir 2)
    for (int w = 1; w < W_; w++)
        mma_step_w<<<gridW, 512, SMEM_W>>>(out, 2, w - 1, w);

    // Scan 4: left (axis W, reverse), w_l (dir 3)
    for (int w = W_ - 2; w >= 0; w--)
        mma_step_w<<<gridW, 512, SMEM_W>>>(out, 3, w + 1, w);
}

// round 17
// speedup vs baseline: 1.1348x; 1.1348x over previous
#include <cuda_runtime.h>
#include <cuda_bf16.h>
#include <cstdint>

// SpatialCNN: 4 directional scans; step: out[p] += relu(conv1d_C2C(out[p_prev]))
// x (B=64, C=128, H=36, W=100), w (C, C, KS=9), fp32, in-place in d_out.
// bf16 hi/lo split (3-MMA) with mma.sync.m16n8k16, fp32 accumulate.
// R16 = composition of measured-best per-shape configs:
//   H-step: R13 config (1024 thr, 4 lg x 8 cg, MF=1, COF=2)  -> 35.9us measured
//   W-step: R6  config (256 thr, 2 lg x 4 cg, MF=2/1, COF=2) -> ~13us measured

#define B_ 64
#define C_ 128
#define H_ 36
#define W_ 100
#define KS_ 9
#define CH_STRIDE (H_ * W_)          // 3600
#define B_STRIDE  (C_ * H_ * W_)     // 460800

#define ROWB 272                     // smem row bytes: 128 bf16 + 16B pad
#define ROWE 136                     // row stride in bf16 elems

// Prepacked weights: [((dir*9+s)*8 + cif)*16 + co8][lane] = uint4
// uint4 = { b0hi, b1hi, b0lo, b1lo } : mma B-fragment (k=16 ci, n=8 co)
__device__ uint4 g_wPack[4 * 9 * 8 * 16 * 32];

__device__ __forceinline__ uint32_t pk_hi(float a, float b) {
    __nv_bfloat16 ha = __float2bfloat16(a), hb = __float2bfloat16(b);
    return (uint32_t)__bfloat16_as_ushort(ha) |
           ((uint32_t)__bfloat16_as_ushort(hb) << 16);
}
__device__ __forceinline__ float bf_res(float v) {     // v - bf16(v)
    return v - __bfloat162float(__float2bfloat16(v));
}

__global__ void prepack_kernel(const float* __restrict__ wd,
                               const float* __restrict__ wu,
                               const float* __restrict__ wr,
                               const float* __restrict__ wl) {
    int idx = blockIdx.x * 256 + threadIdx.x;
    const int total = 4 * 9 * 8 * 16 * 32;
    if (idx >= total) return;
    int lane = idx & 31;
    int fr   = idx >> 5;
    int co8  = fr & 15;
    int cif  = (fr >> 4) & 7;
    int rem  = fr >> 7;              // dir*9 + s
    int s    = rem % 9;
    int dir  = rem / 9;
    const float* w = (dir == 0) ? wd : (dir == 1) ? wu : (dir == 2) ? wr : wl;

    int co = co8 * 8 + (lane >> 2);
    int ci = cif * 16 + (lane & 3) * 2;
    float v00 = w[(co * C_ + ci    ) * KS_ + s];
    float v01 = w[(co * C_ + ci + 1) * KS_ + s];
    float v10 = w[(co * C_ + ci + 8) * KS_ + s];
    float v11 = w[(co * C_ + ci + 9) * KS_ + s];

    uint4 r;
    r.x = pk_hi(v00, v01);
    r.y = pk_hi(v10, v11);
    r.z = pk_hi(bf_res(v00), bf_res(v01));
    r.w = pk_hi(bf_res(v10), bf_res(v11));
    g_wPack[idx] = r;
}

__device__ __forceinline__ void ldsm4(uint32_t a[4], uint32_t addr) {
    asm volatile("ldmatrix.sync.aligned.m8n8.x4.shared.b16 {%0,%1,%2,%3}, [%4];"
                 : "=r"(a[0]), "=r"(a[1]), "=r"(a[2]), "=r"(a[3]) : "r"(addr));
}
__device__ __forceinline__ void mma16816(float c[4], const uint32_t a[4],
                                         uint32_t b0, uint32_t b1) {
    asm volatile(
        "mma.sync.aligned.m16n8k16.row.col.f32.bf16.bf16.f32 "
        "{%0,%1,%2,%3},{%4,%5,%6,%7},{%8,%9},{%0,%1,%2,%3};"
        : "+f"(c[0]), "+f"(c[1]), "+f"(c[2]), "+f"(c[3])
        : "r"(a[0]), "r"(a[1]), "r"(a[2]), "r"(a[3]), "r"(b0), "r"(b1));
}

// One warp's share of a step-GEMM: MF m16-frags (lines) x COF co8-frags.
// B-fragments prefetched 1 idx ahead in registers (R6-proven).
template <int MF, int COF, int L, int ES>
__device__ __forceinline__ void warp_work(
    const unsigned short* sHi, const unsigned short* sLo,
    int rowbase, int co8base, int lane, int dir,
    float* __restrict__ curBase, int line0)
{
    const uint32_t aOff = (uint32_t)(lane & 15) * ROWB + ((lane >> 4) & 1) * 16
                        + (uint32_t)rowbase * ROWB;
    const uint32_t shBase = (uint32_t)__cvta_generic_to_shared(sHi) + aOff;
    const uint32_t slBase = (uint32_t)__cvta_generic_to_shared(sLo) + aOff;

    float acc[MF][COF][4];
#pragma unroll
    for (int mf = 0; mf < MF; mf++)
#pragma unroll
        for (int f = 0; f < COF; f++)
#pragma unroll
            for (int q = 0; q < 4; q++) acc[mf][f][q] = 0.0f;

    const uint4* __restrict__ wp = g_wPack;
    const int dbase = dir * 72;

    uint4 Bc[COF], Bn[COF];
#pragma unroll
    for (int f = 0; f < COF; f++)
        Bc[f] = wp[(dbase * 16 + co8base + f) * 32 + lane];

#pragma unroll 1
    for (int s = 0; s < 9; s++) {
#pragma unroll
        for (int cif = 0; cif < 8; cif++) {
            const int idx  = s * 8 + cif;
            const int nidx = (idx + 1 < 72) ? idx + 1 : idx;
#pragma unroll
            for (int f = 0; f < COF; f++)
                Bn[f] = wp[((dbase + nidx) * 16 + co8base + f) * 32 + lane];

            uint32_t ah[MF][4], al[MF][4];
#pragma unroll
            for (int mf = 0; mf < MF; mf++) {
                uint32_t off = (uint32_t)(s + mf * 16) * ROWB + cif * 32;
                ldsm4(ah[mf], shBase + off);
                ldsm4(al[mf], slBase + off);
            }
#pragma unroll
            for (int mf = 0; mf < MF; mf++)
#pragma unroll
                for (int f = 0; f < COF; f++) {
                    mma16816(acc[mf][f], ah[mf], Bc[f].x, Bc[f].y);  // hi*Whi
                    mma16816(acc[mf][f], ah[mf], Bc[f].z, Bc[f].w);  // hi*Wlo
                    mma16816(acc[mf][f], al[mf], Bc[f].x, Bc[f].y);  // lo*Whi
                }
#pragma unroll
            for (int f = 0; f < COF; f++) Bc[f] = Bn[f];
        }
    }

    // Epilogue: out[cur] += relu(acc), guarded on line < L.
    const int r0 = lane >> 2;
    const int c0 = (lane & 3) * 2;
#pragma unroll
    for (int mf = 0; mf < MF; mf++) {
        const int l0 = line0 + mf * 16 + r0;
        const int l1 = l0 + 8;
#pragma unroll
        for (int f = 0; f < COF; f++) {
            const int co = (co8base + f) * 8 + c0;
            float* pc = curBase + (size_t)co * CH_STRIDE;
            if (l0 < L) {
                float* p = pc + l0 * ES;
                p[0]         += fmaxf(acc[mf][f][0], 0.0f);
                p[CH_STRIDE] += fmaxf(acc[mf][f][1], 0.0f);
            }
            if (l1 < L) {
                float* p = pc + l1 * ES;
                p[0]         += fmaxf(acc[mf][f][2], 0.0f);
                p[CH_STRIDE] += fmaxf(acc[mf][f][3], 0.0f);
            }
        }
    }
}

// Shared staging: prev slab fp32 -> bf16 hi/lo split into [WINR][ROWE] smem.
template <int WINR, int L, int ES, int THREADS>
__device__ __forceinline__ void stage_window(
    unsigned short* sHi, unsigned short* sLo,
    const float* __restrict__ prevBase, int n0, int tid)
{
    for (int i = tid; i < C_ * WINR; i += THREADS) {
        int ci = i / WINR, j = i - ci * WINR;
        int line = n0 - 4 + j;
        float v = 0.0f;
        if (line >= 0 && line < L)
            v = prevBase[ci * CH_STRIDE + line * ES];
        __nv_bfloat16 h = __float2bfloat16(v);
        float r = v - __bfloat162float(h);
        sHi[j * ROWE + ci] = __bfloat16_as_ushort(h);
        sLo[j * ROWE + ci] = __bfloat16_as_ushort(__float2bfloat16(r));
    }
}

// H-step (R13 config): 1024 thr = 32 warps (4 line-groups x 8 co-groups).
// MF=1, COF=2, 8 warps/SMSP. Tile 64 lines x 128 co; grid (2 tiles, 64 b).
#define WINR_H 72
#define SMEM_H (2 * WINR_H * ROWB)
__global__ void __launch_bounds__(1024, 1)
mma_step_h(float* __restrict__ out, int dir, int prevOff, int curOff) {
    extern __shared__ unsigned short smem_u16[];
    unsigned short* sHi = smem_u16;
    unsigned short* sLo = smem_u16 + WINR_H * ROWE;

    const int tid  = threadIdx.x;
    const int lane = tid & 31;
    const int warp = tid >> 5;
    const int b    = blockIdx.y;
    const int n0   = blockIdx.x * 64;

    stage_window<WINR_H, W_, 1, 1024>(sHi, sLo,
        out + (size_t)b * B_STRIDE + prevOff, n0, tid);
    __syncthreads();

    const int lg = warp >> 3;             // 0..3 : 16-line group
    const int cg = warp & 7;              // 0..7 : 2 co8 frags each
    const int line0 = n0 + lg * 16;
    if (line0 >= W_) return;              // dead tail group (tile 1)

    warp_work<1, 2, W_, 1>(sHi, sLo, lg * 16, cg * 2, lane, dir,
                           out + (size_t)b * B_STRIDE + curOff, line0);
}

// W-step (R6 config): 256 thr = 8 warps (2 line-groups x 4 co-groups),
// COF=2, co-half per blockIdx.x. lg0: MF=2 (rows 0-31), lg1: MF=1 (32-47).
#define WINR_W 56
#define SMEM_W (2 * WINR_W * ROWB)
__global__ void __launch_bounds__(256, 1)
mma_step_w(float* __restrict__ out, int dir, int prevOff, int curOff) {
    extern __shared__ unsigned short smem_u16[];
    unsigned short* sHi = smem_u16;
    unsigned short* sLo = smem_u16 + WINR_W * ROWE;

    const int tid  = threadIdx.x;
    const int lane = tid & 31;
    const int warp = tid >> 5;
    const int b    = blockIdx.y;

    stage_window<WINR_W, H_, W_, 256>(sHi, sLo,
        out + (size_t)b * B_STRIDE + prevOff, 0, tid);
    __syncthreads();

    const int lg = warp >> 2;             // 0,1
    const int cg = warp & 3;
    const int co8base = blockIdx.x * 8 + cg * 2;
    float* curBase = out + (size_t)b * B_STRIDE + curOff;

    if (lg == 0)
        warp_work<2, 2, H_, W_>(sHi, sLo, 0, co8base, lane, dir, curBase, 0);
    else
        warp_work<1, 2, H_, W_>(sHi, sLo, 32, co8base, lane, dir, curBase, 32);
}

extern "C" void kernel_launch(void* const* d_in, const int* in_sizes, int n_in,
                              void* d_out, int out_size) {
    const float* x = (const float*)d_in[0];
    float* out = (float*)d_out;
    (void)in_sizes; (void)n_in; (void)out_size;

    // out = x (all scans accumulate in place)
    cudaMemcpyAsync(out, x, (size_t)B_ * C_ * H_ * W_ * sizeof(float),
                    cudaMemcpyDeviceToDevice, 0);

    // Pre-split + fragment-pack all weights (2.36MB, L2-resident)
    prepack_kernel<<<(4 * 9 * 8 * 16 * 32 + 255) / 256, 256>>>(
        (const float*)d_in[1], (const float*)d_in[2],
        (const float*)d_in[3], (const float*)d_in[4]);

    const dim3 gridH(2, B_);   // 2 line-tiles of 64 (second partial), full 128 co
    const dim3 gridW(2, B_);   // 2 co-halves, all 36 lines

    // Scan 1: down (axis H, forward), w_d (dir 0)
    for (int h = 1; h < H_; h++)
        mma_step_h<<<gridH, 1024, SMEM_H>>>(out, 0, (h - 1) * W_, h * W_);

    // Scan 2: up (axis H, reverse), w_u (dir 1)
    for (int h = H_ - 2; h >= 0; h--)
        mma_step_h<<<gridH, 1024, SMEM_H>>>(out, 1, (h + 1) * W_, h * W_);

    // Scan 3: right (axis W, forward), w_r (dir 2)
    for (int w = 1; w < W_; w++)
        mma_step_w<<<gridW, 256, SMEM_W>>>(out, 2, w - 1, w);

    // Scan 4: left (axis W, reverse), w_l (dir 3)
    for (int w = W_ - 2; w >= 0; w--)
        mma_step_w<<<gridW, 256, SMEM_W>>>(out, 3, w + 1, w);
}